// round 13
// baseline (speedup 1.0000x reference)
#include <cuda_runtime.h>
#include <cuda_bf16.h>
#include <cstdint>

// Problem shape (fixed)
#define B   64
#define C   64
#define NQ  32
#define S   1024
#define KD  128          // embedding dim
#define MT  128          // Q rows per block (4 b's * 32 n)
#define NT  128          // doc tokens per s-tile
#define NJ  19           // c-stride / gridDim.y  (16*19 = 304 CTAs ~= 296 slots)
#define PADB 136         // smem row stride in bf16 elems (272 B -> bank+4 per row)
#define TEMP_INV 50.0f

__device__ float g_scores[B * C];
__device__ float g_inv[B];                      // TEMP_INV / len(b)
__device__ __nv_bfloat16 g_qbf[B * NQ * KD];    // 0.5 MB
__device__ __nv_bfloat16 g_dbf[C * S * KD];     // 16 MB

__device__ __forceinline__ uint32_t s2u(const void* p) {
    return (uint32_t)__cvta_generic_to_shared(p);
}
__device__ __forceinline__ void cp_async16(uint32_t dst, const void* src) {
    asm volatile("cp.async.cg.shared.global [%0], [%1], 16;\n"
                 :: "r"(dst), "l"(src));
}
__device__ __forceinline__ uint32_t pack_bf16x2(float lo, float hi) {
    __nv_bfloat162 h = __floats2bfloat162_rn(lo, hi);
    return *reinterpret_cast<uint32_t*>(&h);
}
__device__ __forceinline__ void ldsm_x4(uint32_t addr, uint32_t& r0, uint32_t& r1,
                                        uint32_t& r2, uint32_t& r3) {
    asm volatile("ldmatrix.sync.aligned.m8n8.x4.shared.b16 {%0,%1,%2,%3}, [%4];"
                 : "=r"(r0), "=r"(r1), "=r"(r2), "=r"(r3) : "r"(addr));
}

// ---------------------------------------------------------------------------
// Kernel 0: fp32 -> bf16 conversion (uint4 16B stores) + per-b lengths
// ---------------------------------------------------------------------------
__global__ void convert_bf16_kernel(const float* __restrict__ q,
                                    const float* __restrict__ d)
{
    if (blockIdx.x == 0 && threadIdx.x < B) {
        const int b = threadIdx.x;
        int len = 0;
        #pragma unroll
        for (int n = 0; n < NQ; n++)
            len += (q[(size_t)b * NQ * KD + (size_t)n * KD] != 0.0f) ? 1 : 0;
        g_inv[b] = TEMP_INV / (float)len;
    }

    const size_t nq8 = (size_t)B * NQ * KD / 8;        // 32768
    const size_t nd8 = (size_t)C * S  * KD / 8;        // 1048576
    const size_t stride = (size_t)gridDim.x * blockDim.x;
    const size_t t0 = (size_t)blockIdx.x * blockDim.x + threadIdx.x;
    for (size_t idx = t0; idx < nq8; idx += stride) {
        float4 v0 = reinterpret_cast<const float4*>(q)[2 * idx];
        float4 v1 = reinterpret_cast<const float4*>(q)[2 * idx + 1];
        uint4 o;
        o.x = pack_bf16x2(v0.x, v0.y); o.y = pack_bf16x2(v0.z, v0.w);
        o.z = pack_bf16x2(v1.x, v1.y); o.w = pack_bf16x2(v1.z, v1.w);
        reinterpret_cast<uint4*>(g_qbf)[idx] = o;
    }
    for (size_t idx = t0; idx < nd8; idx += stride) {
        float4 v0 = reinterpret_cast<const float4*>(d)[2 * idx];
        float4 v1 = reinterpret_cast<const float4*>(d)[2 * idx + 1];
        uint4 o;
        o.x = pack_bf16x2(v0.x, v0.y); o.y = pack_bf16x2(v0.z, v0.w);
        o.z = pack_bf16x2(v1.x, v1.y); o.w = pack_bf16x2(v1.z, v1.w);
        reinterpret_cast<uint4*>(g_dbf)[idx] = o;
    }
}

// ---------------------------------------------------------------------------
// Kernel 1: bf16 mma.sync GEMM, fused max/sum epilogue, MULTI-ITEM CTAs.
// CTA (mtile, j) processes c = j, j+NJ, j+2NJ, ... (<C) as one flat,
// never-draining tile stream: Q loaded once, D double-buffer runs
// seamlessly across item boundaries. Mainloop body identical to R12.
// ---------------------------------------------------------------------------
__global__ __launch_bounds__(128, 2)
void colbert_scores_mma(void)
{
    extern __shared__ __nv_bfloat16 shb[];
    __shared__ float red2[2 * MT];              // epilogue scratch (Q stays live)
    const uint32_t qs_u = s2u(shb);
    const uint32_t ds_u = qs_u + MT * PADB * 2; // D double buffer base

    const int mtile = blockIdx.x;       // 0..15
    const int j     = blockIdx.y;       // 0..18
    const int tid   = threadIdx.x;
    const int wid   = tid >> 5;         // 0..3
    const int lane  = tid & 31;
    const int warp_m = wid >> 1;        // 0..1
    const int warp_n = wid & 1;         // 0..1
    const int gID   = lane >> 2;
    const int tig   = lane & 3;

    const int n_items = (j + 3 * NJ < C) ? 4 : 3;   // j<7 -> 4, else 3
    const int n_tiles = n_items * 8;

    const __nv_bfloat16* __restrict__ qbase = g_qbf + (size_t)mtile * MT * KD;

    // ---- load Q tile (once per CTA) ----
    #pragma unroll
    for (int i = 0; i < 16; i++) {
        int idx = i * 128 + tid;
        int row = idx >> 4;
        int c8  = idx & 15;
        cp_async16(qs_u + (row * PADB + c8 * 8) * 2, qbase + (size_t)row * KD + c8 * 8);
    }
    // ---- prefetch first D tile (item 0, t 0) ----
    {
        const __nv_bfloat16* src = g_dbf + (size_t)j * S * KD;
        #pragma unroll
        for (int i = 0; i < 16; i++) {
            int idx = i * 128 + tid;
            int row = idx >> 4;
            int c8  = idx & 15;
            cp_async16(ds_u + (row * PADB + c8 * 8) * 2, src + (size_t)row * KD + c8 * 8);
        }
    }
    asm volatile("cp.async.commit_group;\n");

    // ---- ldmatrix per-lane base addresses (bytes) ----
    uint32_t a_base[4], b_base[4];
    {
        const int arow_l = ((lane >> 3) & 1) * 8 + (lane & 7);
        const int acol_l = 8 * (lane >> 4);
        #pragma unroll
        for (int mt = 0; mt < 4; mt++)
            a_base[mt] = qs_u +
                ((warp_m * 64 + mt * 16 + arow_l) * PADB + acol_l) * 2;
        const int brow_l = ((lane >> 4) & 1) * 8 + (lane & 7);
        const int bcol_l = 8 * ((lane >> 3) & 1);
        #pragma unroll
        for (int np = 0; np < 4; np++)
            b_base[np] = ds_u +
                ((warp_n * 64 + np * 16 + brow_l) * PADB + bcol_l) * 2;
    }

    float runmax[4][2];
    #pragma unroll
    for (int mt = 0; mt < 4; mt++)
        #pragma unroll
        for (int h = 0; h < 2; h++)
            runmax[mt][h] = __int_as_float(0xff800000);

    for (int tt = 0; tt < n_tiles; tt++) {
        const int t = tt & 7;                      // s-tile within item
        if (tt + 1 < n_tiles) {
            // seamless cross-item prefetch of tile tt+1
            const int it1 = (tt + 1) >> 3;
            const int t1  = (tt + 1) & 7;
            const int c1  = j + NJ * it1;
            uint32_t dst = ds_u + ((tt + 1) & 1) * NT * PADB * 2;
            const __nv_bfloat16* src =
                g_dbf + (size_t)c1 * S * KD + (size_t)t1 * NT * KD;
            #pragma unroll
            for (int i = 0; i < 16; i++) {
                int idx = i * 128 + tid;
                int row = idx >> 4;
                int c8  = idx & 15;
                cp_async16(dst + (row * PADB + c8 * 8) * 2,
                           src + (size_t)row * KD + c8 * 8);
            }
            asm volatile("cp.async.commit_group;\n");
            asm volatile("cp.async.wait_group 1;\n");
        } else {
            asm volatile("cp.async.wait_group 0;\n");
        }
        __syncthreads();   // tile tt (and Q on tt=0) visible to all warps

        const uint32_t bufoff = (tt & 1) * NT * PADB * 2;

        float acc[4][8][4];
        #pragma unroll
        for (int mt = 0; mt < 4; mt++)
            #pragma unroll
            for (int nt = 0; nt < 8; nt++)
                #pragma unroll
                for (int r = 0; r < 4; r++) acc[mt][nt][r] = 0.0f;

        #pragma unroll
        for (int ks = 0; ks < 8; ks++) {
            const uint32_t koff = ks * 32;          // 16 bf16 = 32 bytes
            uint32_t a[4][4];
            #pragma unroll
            for (int mt = 0; mt < 4; mt++)
                ldsm_x4(a_base[mt] + koff,
                        a[mt][0], a[mt][1], a[mt][2], a[mt][3]);
            uint32_t bf[8][2];
            #pragma unroll
            for (int np = 0; np < 4; np++)
                ldsm_x4(b_base[np] + bufoff + koff,
                        bf[2*np][0], bf[2*np][1], bf[2*np+1][0], bf[2*np+1][1]);
            #pragma unroll
            for (int mt = 0; mt < 4; mt++)
                #pragma unroll
                for (int nt = 0; nt < 8; nt++) {
                    asm volatile(
                        "mma.sync.aligned.m16n8k16.row.col.f32.bf16.bf16.f32 "
                        "{%0,%1,%2,%3}, {%4,%5,%6,%7}, {%8,%9}, {%0,%1,%2,%3};\n"
                        : "+f"(acc[mt][nt][0]), "+f"(acc[mt][nt][1]),
                          "+f"(acc[mt][nt][2]), "+f"(acc[mt][nt][3])
                        : "r"(a[mt][0]), "r"(a[mt][1]), "r"(a[mt][2]), "r"(a[mt][3]),
                          "r"(bf[nt][0]), "r"(bf[nt][1]));
                }
        }

        // c0,c1 -> row gID; c2,c3 -> row gID+8. Cols irrelevant (max over s).
        #pragma unroll
        for (int mt = 0; mt < 4; mt++) {
            float m0 = __int_as_float(0xff800000);
            float m1 = __int_as_float(0xff800000);
            #pragma unroll
            for (int nt = 0; nt < 8; nt++) {
                m0 = fmaxf(m0, fmaxf(acc[mt][nt][0], acc[mt][nt][1]));
                m1 = fmaxf(m1, fmaxf(acc[mt][nt][2], acc[mt][nt][3]));
            }
            runmax[mt][0] = fmaxf(runmax[mt][0], m0);
            runmax[mt][1] = fmaxf(runmax[mt][1], m1);
        }

        // ---- end of item: reduce + store scores, reset running max ----
        if (t == 7) {
            const int c = j + NJ * (tt >> 3);
            __syncthreads();           // all warps' folds done (also buffer guard)
            #pragma unroll
            for (int mt = 0; mt < 4; mt++)
                #pragma unroll
                for (int h = 0; h < 2; h++) {
                    float m = runmax[mt][h];
                    m = fmaxf(m, __shfl_xor_sync(0xffffffffu, m, 1));
                    m = fmaxf(m, __shfl_xor_sync(0xffffffffu, m, 2));
                    if (tig == 0) {
                        int row = warp_m * 64 + mt * 16 + h * 8 + gID;
                        red2[warp_n * 128 + row] = m;
                    }
                }
            __syncthreads();
            {
                int row = wid * 32 + lane;
                float v = fmaxf(red2[row], red2[128 + row]);
                #pragma unroll
                for (int off = 16; off > 0; off >>= 1)
                    v += __shfl_xor_sync(0xffffffffu, v, off);
                if (lane == 0)
                    g_scores[(mtile * 4 + wid) * C + c] = v;
            }
            #pragma unroll
            for (int mt = 0; mt < 4; mt++)
                #pragma unroll
                for (int h = 0; h < 2; h++)
                    runmax[mt][h] = __int_as_float(0xff800000);
            __syncthreads();           // red2 reads done; also buffer guard
        } else {
            __syncthreads();           // buffer reads done before next prefetch
        }
    }
}

// ---------------------------------------------------------------------------
// Kernel 2: normalize, log-softmax, NLL mean. No q reads (g_inv precomputed).
// ---------------------------------------------------------------------------
__global__ void colbert_loss_kernel(const int* __restrict__ offset_p,
                                    float*     __restrict__ out)
{
    __shared__ float losses[B];
    const int tid  = threadIdx.x;
    const int wid  = tid >> 5;
    const int lane = tid & 31;
    const int label_off = offset_p[0];

    #pragma unroll
    for (int r = 0; r < 4; r++) {
        const int b = wid * 4 + r;
        const float inv = g_inv[b];

        float l0 = g_scores[b * C + lane]      * inv;
        float l1 = g_scores[b * C + 32 + lane] * inv;

        float mx = fmaxf(l0, l1);
        #pragma unroll
        for (int o = 16; o > 0; o >>= 1)
            mx = fmaxf(mx, __shfl_xor_sync(0xffffffffu, mx, o));

        float se = expf(l0 - mx) + expf(l1 - mx);
        #pragma unroll
        for (int o = 16; o > 0; o >>= 1)
            se += __shfl_xor_sync(0xffffffffu, se, o);

        const int label = b + label_off;
        const float ll = (label < 32)
                       ? __shfl_sync(0xffffffffu, l0, label)
                       : __shfl_sync(0xffffffffu, l1, label - 32);
        if (lane == 0)
            losses[b] = -(ll - mx - logf(se));
    }
    __syncthreads();

    if (tid < 32) {
        float v = losses[tid] + losses[tid + 32];
        #pragma unroll
        for (int o = 16; o > 0; o >>= 1)
            v += __shfl_xor_sync(0xffffffffu, v, o);
        if (tid == 0) out[0] = v / (float)B;
    }
}

// ---------------------------------------------------------------------------
extern "C" void kernel_launch(void* const* d_in, const int* in_sizes, int n_in,
                              void* d_out, int out_size)
{
    const float* q   = (const float*)d_in[0];
    const float* d   = (const float*)d_in[1];
    const int*   off = (const int*)  d_in[2];
    float*       out = (float*)d_out;

    const size_t smem_bytes = (size_t)(MT * PADB + 2 * NT * PADB)
                              * sizeof(__nv_bfloat16);   // 104448

    cudaFuncSetAttribute(colbert_scores_mma,
                         cudaFuncAttributeMaxDynamicSharedMemorySize,
                         (int)smem_bytes);

    convert_bf16_kernel<<<1024, 256>>>(q, d);
    dim3 grid(16, NJ);
    colbert_scores_mma<<<grid, 128, smem_bytes>>>();
    colbert_loss_kernel<<<1, 512>>>(off, out);
}

// round 14
// speedup vs baseline: 1.2805x; 1.2805x over previous
#include <cuda_runtime.h>
#include <cuda_bf16.h>
#include <cstdint>

// Problem shape (fixed)
#define B   64
#define C   64
#define NQ  32
#define S   1024
#define KD  128          // embedding dim
#define MT  128          // Q rows per block (4 b's * 32 n)
#define NT  128          // doc tokens per s-tile
#define PADB 136         // smem row stride in bf16 elems (272 B -> bank+4 per row)
#define TEMP_INV 50.0f

__device__ float g_scores[B * C];
__device__ float g_inv[B];                      // TEMP_INV / len(b)
__device__ __nv_bfloat16 g_qbf[B * NQ * KD];    // 0.5 MB
__device__ __nv_bfloat16 g_dbf[C * S * KD];     // 16 MB

__device__ __forceinline__ uint32_t s2u(const void* p) {
    return (uint32_t)__cvta_generic_to_shared(p);
}
__device__ __forceinline__ void cp_async16(uint32_t dst, const void* src) {
    asm volatile("cp.async.cg.shared.global [%0], [%1], 16;\n"
                 :: "r"(dst), "l"(src));
}
__device__ __forceinline__ uint32_t pack_bf16x2(float lo, float hi) {
    __nv_bfloat162 h = __floats2bfloat162_rn(lo, hi);
    return *reinterpret_cast<uint32_t*>(&h);
}
__device__ __forceinline__ void ldsm_x4(uint32_t addr, uint32_t& r0, uint32_t& r1,
                                        uint32_t& r2, uint32_t& r3) {
    asm volatile("ldmatrix.sync.aligned.m8n8.x4.shared.b16 {%0,%1,%2,%3}, [%4];"
                 : "=r"(r0), "=r"(r1), "=r"(r2), "=r"(r3) : "r"(addr));
}

// ---------------------------------------------------------------------------
// Kernel 0: fp32 -> bf16 conversion + per-b lengths.
// MLP=4: each thread handles chunks idx and idx + nd8/2 in lockstep
// (4 independent LDG.128 in flight per iteration instead of 2).
// ---------------------------------------------------------------------------
__global__ void convert_bf16_kernel(const float* __restrict__ q,
                                    const float* __restrict__ d)
{
    if (blockIdx.x == 0 && threadIdx.x < B) {
        const int b = threadIdx.x;
        int len = 0;
        #pragma unroll
        for (int n = 0; n < NQ; n++)
            len += (q[(size_t)b * NQ * KD + (size_t)n * KD] != 0.0f) ? 1 : 0;
        g_inv[b] = TEMP_INV / (float)len;
    }

    const size_t nq8  = (size_t)B * NQ * KD / 8;       // 32768
    const size_t nd8  = (size_t)C * S  * KD / 8;       // 1048576
    const size_t half = nd8 / 2;                       // 524288
    const size_t stride = (size_t)gridDim.x * blockDim.x;   // 262144
    const size_t t0 = (size_t)blockIdx.x * blockDim.x + threadIdx.x;

    // q: one strided pass (nq8 < stride -> at most 1 iteration per thread)
    for (size_t idx = t0; idx < nq8; idx += stride) {
        float4 v0 = reinterpret_cast<const float4*>(q)[2 * idx];
        float4 v1 = reinterpret_cast<const float4*>(q)[2 * idx + 1];
        uint4 o;
        o.x = pack_bf16x2(v0.x, v0.y); o.y = pack_bf16x2(v0.z, v0.w);
        o.z = pack_bf16x2(v1.x, v1.y); o.w = pack_bf16x2(v1.z, v1.w);
        reinterpret_cast<uint4*>(g_qbf)[idx] = o;
    }

    // d: two chunks per iteration -> 4 independent 16B loads in flight
    for (size_t idx = t0; idx < half; idx += stride) {
        const size_t idx2 = idx + half;
        float4 a0 = reinterpret_cast<const float4*>(d)[2 * idx];
        float4 a1 = reinterpret_cast<const float4*>(d)[2 * idx + 1];
        float4 b0 = reinterpret_cast<const float4*>(d)[2 * idx2];
        float4 b1 = reinterpret_cast<const float4*>(d)[2 * idx2 + 1];
        uint4 oa, ob;
        oa.x = pack_bf16x2(a0.x, a0.y); oa.y = pack_bf16x2(a0.z, a0.w);
        oa.z = pack_bf16x2(a1.x, a1.y); oa.w = pack_bf16x2(a1.z, a1.w);
        ob.x = pack_bf16x2(b0.x, b0.y); ob.y = pack_bf16x2(b0.z, b0.w);
        ob.z = pack_bf16x2(b1.x, b1.y); ob.w = pack_bf16x2(b1.z, b1.w);
        reinterpret_cast<uint4*>(g_dbf)[idx]  = oa;
        reinterpret_cast<uint4*>(g_dbf)[idx2] = ob;
    }
}

// ---------------------------------------------------------------------------
// Kernel 1: bf16 mma.sync m16n8k16 GEMM, fused max/sum epilogue (R12 exact).
// Block (mtile, c): 128 Q-rows x all 1024 tokens of doc c (8 s-tiles).
// 4 warps, 2x2 grid, warp tile 64x64, ldmatrix.x4, double-buffered cp.async,
// 2 CTAs/SM.
// ---------------------------------------------------------------------------
__global__ __launch_bounds__(128, 2)
void colbert_scores_mma(void)
{
    extern __shared__ __nv_bfloat16 shb[];
    const uint32_t qs_u = s2u(shb);
    const uint32_t ds_u = qs_u + MT * PADB * 2;        // D double buffer base

    const int mtile = blockIdx.x;       // 0..15
    const int c     = blockIdx.y;       // 0..63
    const int tid   = threadIdx.x;
    const int wid   = tid >> 5;         // 0..3
    const int lane  = tid & 31;
    const int warp_m = wid >> 1;        // 0..1
    const int warp_n = wid & 1;         // 0..1
    const int gID   = lane >> 2;
    const int tig   = lane & 3;

    const __nv_bfloat16* __restrict__ qbase = g_qbf + (size_t)mtile * MT * KD;
    const __nv_bfloat16* __restrict__ dbase = g_dbf + (size_t)c * S * KD;

    // ---- load Q tile (once): 2048 x 16B chunks, 16 per thread ----
    #pragma unroll
    for (int i = 0; i < 16; i++) {
        int idx = i * 128 + tid;
        int row = idx >> 4;
        int c8  = idx & 15;
        cp_async16(qs_u + (row * PADB + c8 * 8) * 2, qbase + (size_t)row * KD + c8 * 8);
    }
    // ---- prefetch D s-tile 0 ----
    #pragma unroll
    for (int i = 0; i < 16; i++) {
        int idx = i * 128 + tid;
        int row = idx >> 4;
        int c8  = idx & 15;
        cp_async16(ds_u + (row * PADB + c8 * 8) * 2, dbase + (size_t)row * KD + c8 * 8);
    }
    asm volatile("cp.async.commit_group;\n");

    // ---- ldmatrix per-lane base addresses (bytes) ----
    uint32_t a_base[4], b_base[4];
    {
        const int arow_l = ((lane >> 3) & 1) * 8 + (lane & 7);
        const int acol_l = 8 * (lane >> 4);
        #pragma unroll
        for (int mt = 0; mt < 4; mt++)
            a_base[mt] = qs_u +
                ((warp_m * 64 + mt * 16 + arow_l) * PADB + acol_l) * 2;
        const int brow_l = ((lane >> 4) & 1) * 8 + (lane & 7);
        const int bcol_l = 8 * ((lane >> 3) & 1);
        #pragma unroll
        for (int np = 0; np < 4; np++)
            b_base[np] = ds_u +
                ((warp_n * 64 + np * 16 + brow_l) * PADB + bcol_l) * 2;
    }

    float runmax[4][2];
    #pragma unroll
    for (int mt = 0; mt < 4; mt++)
        #pragma unroll
        for (int h = 0; h < 2; h++)
            runmax[mt][h] = __int_as_float(0xff800000);

    for (int t = 0; t < S / NT; t++) {
        if (t < S / NT - 1) {
            uint32_t dst = ds_u + ((t + 1) & 1) * NT * PADB * 2;
            const __nv_bfloat16* src = dbase + (size_t)(t + 1) * NT * KD;
            #pragma unroll
            for (int i = 0; i < 16; i++) {
                int idx = i * 128 + tid;
                int row = idx >> 4;
                int c8  = idx & 15;
                cp_async16(dst + (row * PADB + c8 * 8) * 2,
                           src + (size_t)row * KD + c8 * 8);
            }
            asm volatile("cp.async.commit_group;\n");
            asm volatile("cp.async.wait_group 1;\n");
        } else {
            asm volatile("cp.async.wait_group 0;\n");
        }
        __syncthreads();   // tile t (and Q on t=0) visible to all warps

        const uint32_t bufoff = (t & 1) * NT * PADB * 2;

        float acc[4][8][4];
        #pragma unroll
        for (int mt = 0; mt < 4; mt++)
            #pragma unroll
            for (int nt = 0; nt < 8; nt++)
                #pragma unroll
                for (int r = 0; r < 4; r++) acc[mt][nt][r] = 0.0f;

        #pragma unroll
        for (int ks = 0; ks < 8; ks++) {
            const uint32_t koff = ks * 32;          // 16 bf16 = 32 bytes
            uint32_t a[4][4];
            #pragma unroll
            for (int mt = 0; mt < 4; mt++)
                ldsm_x4(a_base[mt] + koff,
                        a[mt][0], a[mt][1], a[mt][2], a[mt][3]);
            uint32_t bf[8][2];
            #pragma unroll
            for (int np = 0; np < 4; np++)
                ldsm_x4(b_base[np] + bufoff + koff,
                        bf[2*np][0], bf[2*np][1], bf[2*np+1][0], bf[2*np+1][1]);
            #pragma unroll
            for (int mt = 0; mt < 4; mt++)
                #pragma unroll
                for (int nt = 0; nt < 8; nt++) {
                    asm volatile(
                        "mma.sync.aligned.m16n8k16.row.col.f32.bf16.bf16.f32 "
                        "{%0,%1,%2,%3}, {%4,%5,%6,%7}, {%8,%9}, {%0,%1,%2,%3};\n"
                        : "+f"(acc[mt][nt][0]), "+f"(acc[mt][nt][1]),
                          "+f"(acc[mt][nt][2]), "+f"(acc[mt][nt][3])
                        : "r"(a[mt][0]), "r"(a[mt][1]), "r"(a[mt][2]), "r"(a[mt][3]),
                          "r"(bf[nt][0]), "r"(bf[nt][1]));
                }
        }

        // c0,c1 -> row gID; c2,c3 -> row gID+8. Cols irrelevant (max over s).
        #pragma unroll
        for (int mt = 0; mt < 4; mt++) {
            float m0 = __int_as_float(0xff800000);
            float m1 = __int_as_float(0xff800000);
            #pragma unroll
            for (int nt = 0; nt < 8; nt++) {
                m0 = fmaxf(m0, fmaxf(acc[mt][nt][0], acc[mt][nt][1]));
                m1 = fmaxf(m1, fmaxf(acc[mt][nt][2], acc[mt][nt][3]));
            }
            runmax[mt][0] = fmaxf(runmax[mt][0], m0);
            runmax[mt][1] = fmaxf(runmax[mt][1], m1);
        }
        __syncthreads();   // buffer reads done before next prefetch overwrites
    }

    // ---- reduce: quad max across tig, publish per (warp_n, row) ----
    float* red = reinterpret_cast<float*>(shb);   // reuse smem: 2*128 floats
    #pragma unroll
    for (int mt = 0; mt < 4; mt++)
        #pragma unroll
        for (int h = 0; h < 2; h++) {
            float m = runmax[mt][h];
            m = fmaxf(m, __shfl_xor_sync(0xffffffffu, m, 1));
            m = fmaxf(m, __shfl_xor_sync(0xffffffffu, m, 2));
            if (tig == 0) {
                int row = warp_m * 64 + mt * 16 + h * 8 + gID;
                red[warp_n * 128 + row] = m;
            }
        }
    __syncthreads();

    // rows wid*32..+31 belong to b_global = mtile*4 + wid; n = lane
    {
        int row = wid * 32 + lane;
        float v = fmaxf(red[row], red[128 + row]);
        #pragma unroll
        for (int off = 16; off > 0; off >>= 1)
            v += __shfl_xor_sync(0xffffffffu, v, off);
        if (lane == 0)
            g_scores[(mtile * 4 + wid) * C + c] = v;
    }
}

// ---------------------------------------------------------------------------
// Kernel 2: normalize, log-softmax, NLL mean. No q reads (g_inv precomputed).
// ---------------------------------------------------------------------------
__global__ void colbert_loss_kernel(const int* __restrict__ offset_p,
                                    float*     __restrict__ out)
{
    __shared__ float losses[B];
    const int tid  = threadIdx.x;
    const int wid  = tid >> 5;
    const int lane = tid & 31;
    const int label_off = offset_p[0];

    #pragma unroll
    for (int r = 0; r < 4; r++) {
        const int b = wid * 4 + r;
        const float inv = g_inv[b];

        float l0 = g_scores[b * C + lane]      * inv;
        float l1 = g_scores[b * C + 32 + lane] * inv;

        float mx = fmaxf(l0, l1);
        #pragma unroll
        for (int o = 16; o > 0; o >>= 1)
            mx = fmaxf(mx, __shfl_xor_sync(0xffffffffu, mx, o));

        float se = expf(l0 - mx) + expf(l1 - mx);
        #pragma unroll
        for (int o = 16; o > 0; o >>= 1)
            se += __shfl_xor_sync(0xffffffffu, se, o);

        const int label = b + label_off;
        const float ll = (label < 32)
                       ? __shfl_sync(0xffffffffu, l0, label)
                       : __shfl_sync(0xffffffffu, l1, label - 32);
        if (lane == 0)
            losses[b] = -(ll - mx - logf(se));
    }
    __syncthreads();

    if (tid < 32) {
        float v = losses[tid] + losses[tid + 32];
        #pragma unroll
        for (int o = 16; o > 0; o >>= 1)
            v += __shfl_xor_sync(0xffffffffu, v, o);
        if (tid == 0) out[0] = v / (float)B;
    }
}

// ---------------------------------------------------------------------------
extern "C" void kernel_launch(void* const* d_in, const int* in_sizes, int n_in,
                              void* d_out, int out_size)
{
    const float* q   = (const float*)d_in[0];
    const float* d   = (const float*)d_in[1];
    const int*   off = (const int*)  d_in[2];
    float*       out = (float*)d_out;

    const size_t smem_bytes = (size_t)(MT * PADB + 2 * NT * PADB)
                              * sizeof(__nv_bfloat16);   // 104448

    cudaFuncSetAttribute(colbert_scores_mma,
                         cudaFuncAttributeMaxDynamicSharedMemorySize,
                         (int)smem_bytes);

    convert_bf16_kernel<<<1024, 256>>>(q, d);
    dim3 grid(16, C);
    colbert_scores_mma<<<grid, 128, smem_bytes>>>();
    colbert_loss_kernel<<<1, 512>>>(off, out);
}

// round 16
// speedup vs baseline: 1.2885x; 1.0062x over previous
#include <cuda_runtime.h>
#include <cuda_bf16.h>
#include <cstdint>

// Problem shape (fixed)
#define B   64
#define C   64
#define NQ  32
#define S   1024
#define KD  128          // embedding dim
#define MT  128          // Q rows per block (4 b's * 32 n)
#define NT  128          // doc tokens per s-tile
#define PADB 136         // smem row stride in bf16 elems (272 B -> bank+4 per row)
#define TEMP_INV 50.0f

__device__ float g_scores[B * C];
__device__ float g_inv[B];                      // TEMP_INV / len(b)
__device__ __nv_bfloat16 g_qbf[B * NQ * KD];    // 0.5 MB
__device__ __nv_bfloat16 g_dbf[C * S * KD];     // 16 MB

__device__ __forceinline__ uint32_t s2u(const void* p) {
    return (uint32_t)__cvta_generic_to_shared(p);
}
__device__ __forceinline__ void cp_async16(uint32_t dst, const void* src) {
    asm volatile("cp.async.cg.shared.global [%0], [%1], 16;\n"
                 :: "r"(dst), "l"(src));
}
__device__ __forceinline__ uint32_t pack_bf16x2(float lo, float hi) {
    __nv_bfloat162 h = __floats2bfloat162_rn(lo, hi);
    return *reinterpret_cast<uint32_t*>(&h);
}
__device__ __forceinline__ void ldsm_x4(uint32_t addr, uint32_t& r0, uint32_t& r1,
                                        uint32_t& r2, uint32_t& r3) {
    asm volatile("ldmatrix.sync.aligned.m8n8.x4.shared.b16 {%0,%1,%2,%3}, [%4];"
                 : "=r"(r0), "=r"(r1), "=r"(r2), "=r"(r3) : "r"(addr));
}

// ---------------------------------------------------------------------------
// Kernel 0: fp32 -> bf16 conversion (uint4 16B stores) + per-b lengths
// ---------------------------------------------------------------------------
__global__ void convert_bf16_kernel(const float* __restrict__ q,
                                    const float* __restrict__ d)
{
    if (blockIdx.x == 0 && threadIdx.x < B) {
        const int b = threadIdx.x;
        int len = 0;
        #pragma unroll
        for (int n = 0; n < NQ; n++)
            len += (q[(size_t)b * NQ * KD + (size_t)n * KD] != 0.0f) ? 1 : 0;
        g_inv[b] = TEMP_INV / (float)len;
    }

    const size_t nq8 = (size_t)B * NQ * KD / 8;        // 32768
    const size_t nd8 = (size_t)C * S  * KD / 8;        // 1048576
    const size_t stride = (size_t)gridDim.x * blockDim.x;
    const size_t t0 = (size_t)blockIdx.x * blockDim.x + threadIdx.x;
    for (size_t idx = t0; idx < nq8; idx += stride) {
        float4 v0 = reinterpret_cast<const float4*>(q)[2 * idx];
        float4 v1 = reinterpret_cast<const float4*>(q)[2 * idx + 1];
        uint4 o;
        o.x = pack_bf16x2(v0.x, v0.y); o.y = pack_bf16x2(v0.z, v0.w);
        o.z = pack_bf16x2(v1.x, v1.y); o.w = pack_bf16x2(v1.z, v1.w);
        reinterpret_cast<uint4*>(g_qbf)[idx] = o;
    }
    for (size_t idx = t0; idx < nd8; idx += stride) {
        float4 v0 = reinterpret_cast<const float4*>(d)[2 * idx];
        float4 v1 = reinterpret_cast<const float4*>(d)[2 * idx + 1];
        uint4 o;
        o.x = pack_bf16x2(v0.x, v0.y); o.y = pack_bf16x2(v0.z, v0.w);
        o.z = pack_bf16x2(v1.x, v1.y); o.w = pack_bf16x2(v1.z, v1.w);
        reinterpret_cast<uint4*>(g_dbf)[idx] = o;
    }
}

// ---------------------------------------------------------------------------
// Kernel 1: bf16 mma.sync m16n8k16 GEMM, fused max/sum epilogue.
// R12 structure with ONE __syncthreads per tile (was two):
//   iter t: wait_group 0 -> sync -> issue prefetch(t+1) -> compute(t).
// Buffer safety: prefetch(t+1) overwrites the buffer of compute(t-1), but all
// warps passed sync(t) only after finishing compute(t-1). compute(t)'s buffer
// is next written by prefetch(t+2), issued after sync(t+1). Both safe.
// ---------------------------------------------------------------------------
__global__ __launch_bounds__(128, 2)
void colbert_scores_mma(void)
{
    extern __shared__ __nv_bfloat16 shb[];
    const uint32_t qs_u = s2u(shb);
    const uint32_t ds_u = qs_u + MT * PADB * 2;        // D double buffer base

    const int mtile = blockIdx.x;       // 0..15
    const int c     = blockIdx.y;       // 0..63
    const int tid   = threadIdx.x;
    const int wid   = tid >> 5;         // 0..3
    const int lane  = tid & 31;
    const int warp_m = wid >> 1;        // 0..1
    const int warp_n = wid & 1;         // 0..1
    const int gID   = lane >> 2;
    const int tig   = lane & 3;

    const __nv_bfloat16* __restrict__ qbase = g_qbf + (size_t)mtile * MT * KD;
    const __nv_bfloat16* __restrict__ dbase = g_dbf + (size_t)c * S * KD;

    // ---- load Q tile + D s-tile 0 (group 0) ----
    #pragma unroll
    for (int i = 0; i < 16; i++) {
        int idx = i * 128 + tid;
        int row = idx >> 4;
        int c8  = idx & 15;
        cp_async16(qs_u + (row * PADB + c8 * 8) * 2, qbase + (size_t)row * KD + c8 * 8);
    }
    #pragma unroll
    for (int i = 0; i < 16; i++) {
        int idx = i * 128 + tid;
        int row = idx >> 4;
        int c8  = idx & 15;
        cp_async16(ds_u + (row * PADB + c8 * 8) * 2, dbase + (size_t)row * KD + c8 * 8);
    }
    asm volatile("cp.async.commit_group;\n");

    // ---- ldmatrix per-lane base addresses (bytes) ----
    uint32_t a_base[4], b_base[4];
    {
        const int arow_l = ((lane >> 3) & 1) * 8 + (lane & 7);
        const int acol_l = 8 * (lane >> 4);
        #pragma unroll
        for (int mt = 0; mt < 4; mt++)
            a_base[mt] = qs_u +
                ((warp_m * 64 + mt * 16 + arow_l) * PADB + acol_l) * 2;
        const int brow_l = ((lane >> 4) & 1) * 8 + (lane & 7);
        const int bcol_l = 8 * ((lane >> 3) & 1);
        #pragma unroll
        for (int np = 0; np < 4; np++)
            b_base[np] = ds_u +
                ((warp_n * 64 + np * 16 + brow_l) * PADB + bcol_l) * 2;
    }

    float runmax[4][2];
    #pragma unroll
    for (int mt = 0; mt < 4; mt++)
        #pragma unroll
        for (int h = 0; h < 2; h++)
            runmax[mt][h] = __int_as_float(0xff800000);

    for (int t = 0; t < S / NT; t++) {
        asm volatile("cp.async.wait_group 0;\n");   // tile t (and Q at t=0)
        __syncthreads();   // data visible; all warps done with compute(t-1)

        if (t < S / NT - 1) {
            uint32_t dst = ds_u + ((t + 1) & 1) * NT * PADB * 2;
            const __nv_bfloat16* src = dbase + (size_t)(t + 1) * NT * KD;
            #pragma unroll
            for (int i = 0; i < 16; i++) {
                int idx = i * 128 + tid;
                int row = idx >> 4;
                int c8  = idx & 15;
                cp_async16(dst + (row * PADB + c8 * 8) * 2,
                           src + (size_t)row * KD + c8 * 8);
            }
            asm volatile("cp.async.commit_group;\n");
        }

        const uint32_t bufoff = (t & 1) * NT * PADB * 2;

        float acc[4][8][4];
        #pragma unroll
        for (int mt = 0; mt < 4; mt++)
            #pragma unroll
            for (int nt = 0; nt < 8; nt++)
                #pragma unroll
                for (int r = 0; r < 4; r++) acc[mt][nt][r] = 0.0f;

        #pragma unroll
        for (int ks = 0; ks < 8; ks++) {
            const uint32_t koff = ks * 32;          // 16 bf16 = 32 bytes
            uint32_t a[4][4];
            #pragma unroll
            for (int mt = 0; mt < 4; mt++)
                ldsm_x4(a_base[mt] + koff,
                        a[mt][0], a[mt][1], a[mt][2], a[mt][3]);
            uint32_t bf[8][2];
            #pragma unroll
            for (int np = 0; np < 4; np++)
                ldsm_x4(b_base[np] + bufoff + koff,
                        bf[2*np][0], bf[2*np][1], bf[2*np+1][0], bf[2*np+1][1]);
            #pragma unroll
            for (int mt = 0; mt < 4; mt++)
                #pragma unroll
                for (int nt = 0; nt < 8; nt++) {
                    asm volatile(
                        "mma.sync.aligned.m16n8k16.row.col.f32.bf16.bf16.f32 "
                        "{%0,%1,%2,%3}, {%4,%5,%6,%7}, {%8,%9}, {%0,%1,%2,%3};\n"
                        : "+f"(acc[mt][nt][0]), "+f"(acc[mt][nt][1]),
                          "+f"(acc[mt][nt][2]), "+f"(acc[mt][nt][3])
                        : "r"(a[mt][0]), "r"(a[mt][1]), "r"(a[mt][2]), "r"(a[mt][3]),
                          "r"(bf[nt][0]), "r"(bf[nt][1]));
                }
        }

        // c0,c1 -> row gID; c2,c3 -> row gID+8. Cols irrelevant (max over s).
        #pragma unroll
        for (int mt = 0; mt < 4; mt++) {
            float m0 = __int_as_float(0xff800000);
            float m1 = __int_as_float(0xff800000);
            #pragma unroll
            for (int nt = 0; nt < 8; nt++) {
                m0 = fmaxf(m0, fmaxf(acc[mt][nt][0], acc[mt][nt][1]));
                m1 = fmaxf(m1, fmaxf(acc[mt][nt][2], acc[mt][nt][3]));
            }
            runmax[mt][0] = fmaxf(runmax[mt][0], m0);
            runmax[mt][1] = fmaxf(runmax[mt][1], m1);
        }
        // no trailing sync: next iteration's top sync provides the guard
    }

    __syncthreads();   // all compute(7) done before epilogue reuses Q smem

    // ---- reduce: quad max across tig, publish per (warp_n, row) ----
    float* red = reinterpret_cast<float*>(shb);   // reuse smem: 2*128 floats
    #pragma unroll
    for (int mt = 0; mt < 4; mt++)
        #pragma unroll
        for (int h = 0; h < 2; h++) {
            float m = runmax[mt][h];
            m = fmaxf(m, __shfl_xor_sync(0xffffffffu, m, 1));
            m = fmaxf(m, __shfl_xor_sync(0xffffffffu, m, 2));
            if (tig == 0) {
                int row = warp_m * 64 + mt * 16 + h * 8 + gID;
                red[warp_n * 128 + row] = m;
            }
        }
    __syncthreads();

    // rows wid*32..+31 belong to b_global = mtile*4 + wid; n = lane
    {
        int row = wid * 32 + lane;
        float v = fmaxf(red[row], red[128 + row]);
        #pragma unroll
        for (int off = 16; off > 0; off >>= 1)
            v += __shfl_xor_sync(0xffffffffu, v, off);
        if (lane == 0)
            g_scores[(mtile * 4 + wid) * C + c] = v;
    }
}

// ---------------------------------------------------------------------------
// Kernel 2: normalize, log-softmax, NLL mean. No q reads (g_inv precomputed).
// ---------------------------------------------------------------------------
__global__ void colbert_loss_kernel(const int* __restrict__ offset_p,
                                    float*     __restrict__ out)
{
    __shared__ float losses[B];
    const int tid  = threadIdx.x;
    const int wid  = tid >> 5;
    const int lane = tid & 31;
    const int label_off = offset_p[0];

    #pragma unroll
    for (int r = 0; r < 4; r++) {
        const int b = wid * 4 + r;
        const float inv = g_inv[b];

        float l0 = g_scores[b * C + lane]      * inv;
        float l1 = g_scores[b * C + 32 + lane] * inv;

        float mx = fmaxf(l0, l1);
        #pragma unroll
        for (int o = 16; o > 0; o >>= 1)
            mx = fmaxf(mx, __shfl_xor_sync(0xffffffffu, mx, o));

        float se = expf(l0 - mx) + expf(l1 - mx);
        #pragma unroll
        for (int o = 16; o > 0; o >>= 1)
            se += __shfl_xor_sync(0xffffffffu, se, o);

        const int label = b + label_off;
        const float ll = (label < 32)
                       ? __shfl_sync(0xffffffffu, l0, label)
                       : __shfl_sync(0xffffffffu, l1, label - 32);
        if (lane == 0)
            losses[b] = -(ll - mx - logf(se));
    }
    __syncthreads();

    if (tid < 32) {
        float v = losses[tid] + losses[tid + 32];
        #pragma unroll
        for (int o = 16; o > 0; o >>= 1)
            v += __shfl_xor_sync(0xffffffffu, v, o);
        if (tid == 0) out[0] = v / (float)B;
    }
}

// ---------------------------------------------------------------------------
extern "C" void kernel_launch(void* const* d_in, const int* in_sizes, int n_in,
                              void* d_out, int out_size)
{
    const float* q   = (const float*)d_in[0];
    const float* d   = (const float*)d_in[1];
    const int*   off = (const int*)  d_in[2];
    float*       out = (float*)d_out;

    const size_t smem_bytes = (size_t)(MT * PADB + 2 * NT * PADB)
                              * sizeof(__nv_bfloat16);   // 104448

    cudaFuncSetAttribute(colbert_scores_mma,
                         cudaFuncAttributeMaxDynamicSharedMemorySize,
                         (int)smem_bytes);

    convert_bf16_kernel<<<2048, 256>>>(q, d);
    dim3 grid(16, C);
    colbert_scores_mma<<<grid, 128, smem_bytes>>>();
    colbert_loss_kernel<<<1, 512>>>(off, out);
}